// round 15
// baseline (speedup 1.0000x reference)
#include <cuda_runtime.h>
#include <cuda.h>
#include <cuda_bf16.h>
#include <cstdint>

#define NROWS 8192
#define MCOLS 8192
#define D_DIM 256
#define GAMMA_F (1.0f/256.0f)

// ---- tc path: 128(M) x 256(N) per CTA, bf16 SW64 TMA, 4-stage, cluster(1,2) B-multicast ----
#define BM 128
#define BN 256
#define BK 32              // bf16 elements per k-block = 64 bytes per row (SW64)
#define NBLK (D_DIM/BK)    // 8
#define NBUF 4

#define A_BYTES 8192       // 128 rows x 64B
#define B_BYTES 16384      // 256 rows x 64B
#define BLK_BYTES (A_BYTES + B_BYTES)

// smem byte offsets -- all mbars one-shot
#define SM_FULLS  0        // 8 mbars [0,64)
#define SM_BDONE  64       // 8 mbars [64,128)
#define SM_FIN    128
#define SM_TMEMP  136
#define SM_SSQ    256      // 256 floats [256,1280)
#define SM_BUF0   2048     // per buf: A 8KB then B 16KB
#define BUF_SZ    24576
#define SM_TOTAL  (SM_BUF0 + NBUF*BUF_SZ)   // 100352 -> occ 2

// bf16 idesc
#define IDESC ((1u<<4) | (1u<<7) | (1u<<10) | ((BN/8u)<<17) | ((BM/16u)<<24))

// SW64 K-major smem descriptor: layout=4, version=1, SBO=32, LBO=1
#define DESC_BASE ((4ull<<61) | (1ull<<46) | (32ull<<32) | (1ull<<16))
#define MAKE_DESC(a) (DESC_BASE | ((uint64_t)((a) >> 4) & 0x3FFF))

#if defined(__CUDA_ARCH__) && (defined(__CUDA_ARCH_FEAT_SM103_ALL) || defined(__CUDA_ARCH_FEAT_SM100_ALL) || (defined(__CUDA_ARCH_SPECIFIC__) && (__CUDA_ARCH_SPECIFIC__ >= 1000)))
#define TC_OK 1
#else
#define TC_OK 0
#endif

__device__ float g_xsq[NROWS];
__device__ float g_ssq[MCOLS];
__device__ __nv_bfloat16 g_xb[NROWS * D_DIM];
__device__ __nv_bfloat16 g_sb[MCOLS * D_DIM];

// ---------------- PTX helpers ----------------
__device__ __forceinline__ uint32_t smem_u32(const void* p) {
    uint32_t a;
    asm("{ .reg .u64 t; cvta.to.shared.u64 t, %1; cvt.u32.u64 %0, t; }" : "=r"(a) : "l"(p));
    return a;
}
__device__ __forceinline__ uint32_t ctarank() {
    uint32_t r;
    asm("mov.u32 %0, %%cluster_ctarank;" : "=r"(r));
    return r;
}
__device__ __forceinline__ void cluster_sync() {
    asm volatile("barrier.cluster.arrive.aligned;" ::: "memory");
    asm volatile("barrier.cluster.wait.aligned;" ::: "memory");
}
__device__ __forceinline__ void mbar_init(uint32_t a, uint32_t cnt) {
    asm volatile("mbarrier.init.shared.b64 [%0], %1;" :: "r"(a), "r"(cnt) : "memory");
}
__device__ __forceinline__ void mbar_expect_tx(uint32_t a, uint32_t bytes) {
    asm volatile("mbarrier.arrive.expect_tx.shared.b64 _, [%0], %1;" :: "r"(a), "r"(bytes) : "memory");
}
__device__ __forceinline__ void mbar_wait(uint32_t a, uint32_t parity) {
    asm volatile(
        "{\n\t.reg .pred P1;\n\t"
        "WL_%=:\n\t"
        "mbarrier.try_wait.parity.acquire.cta.shared::cta.b64 P1, [%0], %1, 0x989680;\n\t"
        "@P1 bra.uni WD_%=;\n\t"
        "bra.uni WL_%=;\n\t"
        "WD_%=:\n\t}"
        :: "r"(a), "r"(parity) : "memory");
}
__device__ __forceinline__ void tma_load_2d(uint32_t smem_addr, const CUtensorMap* map,
                                            int x, int y, uint32_t mbar) {
#if TC_OK
    asm volatile(
        "cp.async.bulk.tensor.2d.shared::cta.global.tile.mbarrier::complete_tx::bytes "
        "[%0], [%1, {%2, %3}], [%4];"
        :: "r"(smem_addr), "l"(map), "r"(x), "r"(y), "r"(mbar) : "memory");
#endif
}
__device__ __forceinline__ void tma_load_2d_mc(uint32_t smem_addr, const CUtensorMap* map,
                                               int x, int y, uint32_t mbar, uint16_t mask) {
#if TC_OK
    asm volatile(
        "cp.async.bulk.tensor.2d.shared::cluster.global.tile.mbarrier::complete_tx::bytes.multicast::cluster "
        "[%0], [%1, {%2, %3}], [%4], %5;"
        :: "r"(smem_addr), "l"(map), "r"(x), "r"(y), "r"(mbar), "h"(mask) : "memory");
#endif
}
__device__ __forceinline__ void tmem_alloc(uint32_t smem_res, uint32_t ncols) {
#if TC_OK
    asm volatile("tcgen05.alloc.cta_group::1.sync.aligned.shared::cta.b32 [%0], %1;"
                 :: "r"(smem_res), "r"(ncols) : "memory");
#endif
}
__device__ __forceinline__ void tmem_relinq() {
#if TC_OK
    asm volatile("tcgen05.relinquish_alloc_permit.cta_group::1.sync.aligned;");
#endif
}
__device__ __forceinline__ void tmem_dealloc(uint32_t tmem, uint32_t ncols) {
#if TC_OK
    asm volatile("tcgen05.dealloc.cta_group::1.sync.aligned.b32 %0, %1;" :: "r"(tmem), "r"(ncols));
#endif
}
__device__ __forceinline__ void mma_commit(uint32_t mbar) {
#if TC_OK
    asm volatile("tcgen05.commit.cta_group::1.mbarrier::arrive::one.shared::cluster.b64 [%0];"
                 :: "r"(mbar) : "memory");
#endif
}
__device__ __forceinline__ void mma_commit_mc(uint32_t mbar, uint16_t mask) {
#if TC_OK
    asm volatile(
        "tcgen05.commit.cta_group::1.mbarrier::arrive::one.shared::cluster.multicast::cluster.b64 [%0], %1;"
        :: "r"(mbar), "h"(mask) : "memory");
#endif
}
__device__ __forceinline__ void mma_bf16_ss(uint32_t d_tmem, uint64_t a_desc, uint64_t b_desc,
                                            uint32_t idesc, bool accum) {
#if TC_OK
    uint32_t en = accum ? 1u : 0u;
    asm volatile(
        "{\n\t.reg .pred p;\n\tsetp.ne.u32 p, %5, 0;\n\t"
        "tcgen05.mma.cta_group::1.kind::f16 [%0], %1, %2, %3, {%4, %4, %4, %4}, p;\n\t}"
        :: "r"(d_tmem), "l"(a_desc), "l"(b_desc), "r"(idesc), "r"(0u), "r"(en)
        : "memory");
#endif
}
__device__ __forceinline__ void ldtm_x32(uint32_t* r, uint32_t tmem) {
#if TC_OK
    asm volatile(
        "tcgen05.ld.sync.aligned.32x32b.x32.b32 "
        "{%0, %1, %2, %3, %4, %5, %6, %7, %8, %9, %10, %11, %12, %13, %14, %15, "
        " %16, %17, %18, %19, %20, %21, %22, %23, %24, %25, %26, %27, %28, %29, %30, %31}, [%32];"
        : "=r"(r[0]), "=r"(r[1]), "=r"(r[2]), "=r"(r[3]), "=r"(r[4]), "=r"(r[5]), "=r"(r[6]), "=r"(r[7]),
          "=r"(r[8]), "=r"(r[9]), "=r"(r[10]), "=r"(r[11]), "=r"(r[12]), "=r"(r[13]), "=r"(r[14]), "=r"(r[15]),
          "=r"(r[16]), "=r"(r[17]), "=r"(r[18]), "=r"(r[19]), "=r"(r[20]), "=r"(r[21]), "=r"(r[22]), "=r"(r[23]),
          "=r"(r[24]), "=r"(r[25]), "=r"(r[26]), "=r"(r[27]), "=r"(r[28]), "=r"(r[29]), "=r"(r[30]), "=r"(r[31])
        : "r"(tmem));
#endif
}
__device__ __forceinline__ void tmem_wait_ld() {
#if TC_OK
    asm volatile("tcgen05.wait::ld.sync.aligned;" ::: "memory");
#endif
}
__device__ __forceinline__ void fence_after() {
#if TC_OK
    asm volatile("tcgen05.fence::after_thread_sync;" ::: "memory");
#endif
}
__device__ __forceinline__ void fence_before() {
#if TC_OK
    asm volatile("tcgen05.fence::before_thread_sync;" ::: "memory");
#endif
}
__device__ __forceinline__ void fence_proxy() {
    asm volatile("fence.proxy.async.shared::cta;" ::: "memory");
}
__device__ __forceinline__ void stg_cs_v4(float* p, float a, float b, float c, float d) {
    asm volatile("st.global.cs.v4.f32 [%0], {%1, %2, %3, %4};"
                 :: "l"(p), "f"(a), "f"(b), "f"(c), "f"(d) : "memory");
}

// ---- packed f32x2 helpers ----
__device__ __forceinline__ uint64_t pack2(uint32_t lo, uint32_t hi) {
    uint64_t r;
    asm("mov.b64 %0, {%1, %2};" : "=l"(r) : "r"(lo), "r"(hi));
    return r;
}
__device__ __forceinline__ void unpack2(uint32_t& lo, uint32_t& hi, uint64_t v) {
    asm("mov.b64 {%0, %1}, %2;" : "=r"(lo), "=r"(hi) : "l"(v));
}
#if TC_OK
#define FMA2(d, a, b, c) asm("fma.rn.f32x2 %0, %1, %2, %3;" : "=l"(d) : "l"(a), "l"(b), "l"(c))
#define ADD2(d, a, b)    asm("add.rn.f32x2 %0, %1, %2;" : "=l"(d) : "l"(a), "l"(b))
#endif

// ---------------- prep kernel: fp32 -> bf16 + row norms, 2 rows per warp ----------------
__global__ void rbf_prep_kernel(const float* __restrict__ X, const float* __restrict__ S,
                                int N, int M) {
    int warp = (blockIdx.x * blockDim.x + threadIdx.x) >> 5;
    int lane = threadIdx.x & 31;
    int r0 = warp * 2;
    if (r0 >= N + M) return;

    const bool isX = r0 < N;
    const int row0 = isX ? r0 : r0 - N;
    const float* srcBase = isX ? X : S;
    __nv_bfloat16* dstBase = isX ? g_xb : g_sb;

    const float* s0 = srcBase + (size_t)row0 * D_DIM + lane * 8;
    const float* s1 = s0 + D_DIM;

    float4 v0 = *(const float4*)(s0);
    float4 v1 = *(const float4*)(s0 + 4);
    float4 v2 = *(const float4*)(s1);
    float4 v3 = *(const float4*)(s1 + 4);

    float sa = v0.x * v0.x + v0.y * v0.y + v0.z * v0.z + v0.w * v0.w
             + v1.x * v1.x + v1.y * v1.y + v1.z * v1.z + v1.w * v1.w;
    float sb2 = v2.x * v2.x + v2.y * v2.y + v2.z * v2.z + v2.w * v2.w
              + v3.x * v3.x + v3.y * v3.y + v3.z * v3.z + v3.w * v3.w;

    __nv_bfloat162 b0 = __floats2bfloat162_rn(v0.x, v0.y);
    __nv_bfloat162 b1 = __floats2bfloat162_rn(v0.z, v0.w);
    __nv_bfloat162 b2 = __floats2bfloat162_rn(v1.x, v1.y);
    __nv_bfloat162 b3 = __floats2bfloat162_rn(v1.z, v1.w);
    uint4 p0;
    p0.x = *(uint32_t*)&b0; p0.y = *(uint32_t*)&b1;
    p0.z = *(uint32_t*)&b2; p0.w = *(uint32_t*)&b3;
    *(uint4*)(dstBase + (size_t)row0 * D_DIM + lane * 8) = p0;

    __nv_bfloat162 c0 = __floats2bfloat162_rn(v2.x, v2.y);
    __nv_bfloat162 c1 = __floats2bfloat162_rn(v2.z, v2.w);
    __nv_bfloat162 c2 = __floats2bfloat162_rn(v3.x, v3.y);
    __nv_bfloat162 c3 = __floats2bfloat162_rn(v3.z, v3.w);
    uint4 p1;
    p1.x = *(uint32_t*)&c0; p1.y = *(uint32_t*)&c1;
    p1.z = *(uint32_t*)&c2; p1.w = *(uint32_t*)&c3;
    *(uint4*)(dstBase + (size_t)(row0 + 1) * D_DIM + lane * 8) = p1;

#pragma unroll
    for (int o = 16; o > 0; o >>= 1) {
        sa += __shfl_xor_sync(0xffffffffu, sa, o);
        sb2 += __shfl_xor_sync(0xffffffffu, sb2, o);
    }
    if (lane == 0) {
        float* dq = isX ? g_xsq : g_ssq;
        dq[row0] = sa;
        dq[row0 + 1] = sb2;
    }
}

// ---------------- fused TMA(bf16,SW64,B-multicast) + tcgen05 GEMM + RBF epilogue ----------------
__global__ void __launch_bounds__(256, 2) __cluster_dims__(1, 2, 1)
rbf_tc_kernel(const __grid_constant__ CUtensorMap tma_a,
              const __grid_constant__ CUtensorMap tma_b,
              float* __restrict__ out) {
#if TC_OK
    extern __shared__ char smem[];
    const uint32_t sb = smem_u32(smem);
    const int tid = threadIdx.x;
    const int wid = tid >> 5, lane = tid & 31;
    const uint32_t rank = ctarank();       // 0 or 1 within (1,2,1) cluster
    const int rowBase = blockIdx.y * BM;   // differs across cluster ranks
    const int colBase = blockIdx.x * BN;   // shared across cluster -> shared B

    const float A_CONST = -0.005635527503472513f;    // -gamma * log2(e)

    ((float*)(smem + SM_SSQ))[tid] = A_CONST * g_ssq[colBase + tid];
    const int sub = wid & 3;
    const int myrow = rowBase + sub * 32 + lane;
    const float xsA = A_CONST * g_xsq[myrow];

    if (tid == 0) {
#pragma unroll
        for (int i = 0; i < NBLK; i++) {
            mbar_init(sb + SM_FULLS + i * 8, 1);
            mbar_init(sb + SM_BDONE + i * 8, 2);   // both CTAs' MMA commits
        }
        mbar_init(sb + SM_FIN, 1);
        fence_proxy();
    }
    if (wid == 0) { tmem_alloc(sb + SM_TMEMP, 256); tmem_relinq(); }
    __syncthreads();
    cluster_sync();   // peer mbars initialized before any multicast tx

    uint32_t tmem;
    asm volatile("ld.shared.b32 %0, [%1];" : "=r"(tmem) : "r"(sb + SM_TMEMP));

    if (tid == 0) {
        uint32_t abuf[NBUF], bbuf[NBUF];
        uint64_t ad[NBUF], bd[NBUF];
#pragma unroll
        for (int b = 0; b < NBUF; b++) {
            abuf[b] = sb + SM_BUF0 + b * BUF_SZ;
            bbuf[b] = abuf[b] + A_BYTES;
            ad[b] = MAKE_DESC(abuf[b]);
            bd[b] = MAKE_DESC(bbuf[b]);
        }

        // prologue: k-blocks 0..3 into bufs 0..3
#pragma unroll
        for (int p = 0; p < NBUF; p++) {
            mbar_expect_tx(sb + SM_FULLS + p * 8, BLK_BYTES);
            tma_load_2d(abuf[p], &tma_a, p * BK, rowBase, sb + SM_FULLS + p * 8);
            if (rank == 0)
                tma_load_2d_mc(bbuf[p], &tma_b, p * BK, colBase, sb + SM_FULLS + p * 8, 0x3);
        }

#pragma unroll
        for (int i = 0; i < NBLK; i++) {
            const int buf = i & 3;
            mbar_wait(sb + SM_FULLS + i * 8, 0);      // one-shot parity 0
#pragma unroll
            for (int s = 0; s < 2; s++)               // 2 x K=16 bf16 steps
                mma_bf16_ss(tmem, ad[buf] + s * 2, bd[buf] + s * 2, IDESC, (i > 0) || (s > 0));
            if (i < NBLK - 4) mma_commit_mc(sb + SM_BDONE + i * 8, 0x3);  // both CTAs see it
            if (i == NBLK - 1) mma_commit(sb + SM_FIN);
            if (i + 4 < NBLK) {
                mbar_wait(sb + SM_BDONE + i * 8, 0);  // BOTH CTAs done with buf
                const int k0 = (i + 4) * BK;
                mbar_expect_tx(sb + SM_FULLS + (i + 4) * 8, BLK_BYTES);
                tma_load_2d(abuf[buf], &tma_a, k0, rowBase, sb + SM_FULLS + (i + 4) * 8);
                if (rank == 0)
                    tma_load_2d_mc(bbuf[buf], &tma_b, k0, colBase, sb + SM_FULLS + (i + 4) * 8, 0x3);
            }
        }
    }

    mbar_wait(sb + SM_FIN, 0);
    fence_after();

    // ---- packed f32x2 epilogue, LDTM double-buffered ----
    const float C2 = -2.0f * A_CONST;
    const float MAGIC = 12582912.0f;
    const uint64_t xsAp   = pack2(__float_as_uint(xsA), __float_as_uint(xsA));
    const uint64_t C2p    = pack2(__float_as_uint(C2), __float_as_uint(C2));
    const uint64_t MAGICp = pack2(__float_as_uint(MAGIC), __float_as_uint(MAGIC));
    const uint64_t NMAGp  = pack2(__float_as_uint(-MAGIC), __float_as_uint(-MAGIC));
    const uint64_t NEG1p  = pack2(__float_as_uint(-1.0f), __float_as_uint(-1.0f));
    const uint64_t C4p  = pack2(__float_as_uint(9.6181291e-3f), __float_as_uint(9.6181291e-3f));
    const uint64_t C3p  = pack2(__float_as_uint(5.5504115e-2f), __float_as_uint(5.5504115e-2f));
    const uint64_t C2pp = pack2(__float_as_uint(2.4022649e-1f), __float_as_uint(2.4022649e-1f));
    const uint64_t C1p  = pack2(__float_as_uint(6.9314718e-1f), __float_as_uint(6.9314718e-1f));
    const uint64_t C0p  = pack2(__float_as_uint(1.0f), __float_as_uint(1.0f));

    const char* ssqA = (const char*)(smem + SM_SSQ);
    const int half = wid >> 2;

    uint32_t regsA[32], regsB[32];
    ldtm_x32(regsA, tmem + half * 128);
    tmem_wait_ld();

#pragma unroll
    for (int ch = 0; ch < 4; ch++) {
        uint32_t* cur = (ch & 1) ? regsB : regsA;
        uint32_t* nxt = (ch & 1) ? regsA : regsB;
        const int col0 = half * 128 + ch * 32;
        if (ch < 3) ldtm_x32(nxt, tmem + col0 + 32);
        const size_t obase = (size_t)myrow * MCOLS + colBase + col0;
#pragma unroll
        for (int j4 = 0; j4 < 8; j4++) {
            float vv[4];
#pragma unroll
            for (int jp = 0; jp < 2; jp++) {
                const int j = j4 * 4 + jp * 2;
                uint64_t sAp = *(const uint64_t*)(ssqA + (col0 + j) * 4);
                uint64_t crp = pack2(cur[j], cur[j + 1]);
                uint64_t up, tp, zp, yp, rp, pp;
                ADD2(up, sAp, xsAp);
                FMA2(tp, crp, C2p, up);
                ADD2(zp, tp, MAGICp);
                ADD2(yp, zp, NMAGp);
                FMA2(rp, yp, NEG1p, tp);
                FMA2(pp, rp, C4p, C3p);
                FMA2(pp, rp, pp, C2pp);
                FMA2(pp, rp, pp, C1p);
                FMA2(pp, rp, pp, C0p);
                uint32_t z0, z1, p0, p1;
                unpack2(z0, z1, zp);
                unpack2(p0, p1, pp);
                vv[jp * 2 + 0] = __int_as_float((int)p0 + ((int)z0 << 23));
                vv[jp * 2 + 1] = __int_as_float((int)p1 + ((int)z1 << 23));
            }
            stg_cs_v4(out + obase + j4 * 4, vv[0], vv[1], vv[2], vv[3]);
        }
        if (ch < 3) tmem_wait_ld();
    }

    fence_before();
    __syncthreads();
    if (wid == 0) tmem_dealloc(tmem, 256);
    cluster_sync();   // no CTA exits while peer multicast/commit may target it
#endif  // TC_OK
}

// ---------------- SIMT fallback (proven R1 kernel) ----------------
#define FBM 128
#define FBN 128
#define FBK 32
#define FTM 8
#define FTN 8
#define FPAD 4

__global__ void __launch_bounds__(256, 2)
rbf_gemm_fallback(const float* __restrict__ X, const float* __restrict__ S,
                  float* __restrict__ out, int N, int M) {
    __shared__ float As[FBK][FBM + FPAD];
    __shared__ float Bs[FBK][FBN + FPAD];

    const int tid = threadIdx.x;
    const int tx = tid & 15;
    const int ty = tid >> 4;
    const int rowBase = blockIdx.y * FBM;
    const int colBase = blockIdx.x * FBN;

    float acc[FTM][FTN];
#pragma unroll
    for (int m = 0; m < FTM; m++)
#pragma unroll
        for (int n = 0; n < FTN; n++) acc[m][n] = 0.0f;

    for (int k0 = 0; k0 < D_DIM; k0 += FBK) {
#pragma unroll
        for (int i = 0; i < 4; i++) {
            int f = tid + i * 256;
            int r = f >> 3;
            int c = (f & 7) * 4;
            float4 a = *(const float4*)(X + (size_t)(rowBase + r) * D_DIM + k0 + c);
            As[c + 0][r] = a.x; As[c + 1][r] = a.y;
            As[c + 2][r] = a.z; As[c + 3][r] = a.w;
            float4 b = *(const float4*)(S + (size_t)(colBase + r) * D_DIM + k0 + c);
            Bs[c + 0][r] = b.x; Bs[c + 1][r] = b.y;
            Bs[c + 2][r] = b.z; Bs[c + 3][r] = b.w;
        }
        __syncthreads();

#pragma unroll 8
        for (int k = 0; k < FBK; k++) {
            float ar[FTM], br[FTN];
            float4 a0 = *(const float4*)&As[k][ty * 4];
            float4 a1 = *(const float4*)&As[k][ty * 4 + 64];
            float4 b0 = *(const float4*)&Bs[k][tx * 4];
            float4 b1 = *(const float4*)&Bs[k][tx * 4 + 64];
            ar[0] = a0.x; ar[1] = a0.y; ar[2] = a0.z; ar[3] = a0.w;
            ar[4] = a1.x; ar[5] = a1.y; ar[6] = a1.z; ar[7] = a1.w;
            br[0] = b0.x; br[1] = b0.y; br[2] = b0.z; br[3] = b0.w;
            br[4] = b1.x; br[5] = b1.y; br[6] = b1.z; br[7] = b1.w;
#pragma unroll
            for (int m = 0; m < FTM; m++)
#pragma unroll
                for (int n = 0; n < FTN; n++)
                    acc[m][n] = fmaf(ar[m], br[n], acc[m][n]);
        }
        __syncthreads();
    }

    float xsr[FTM], ssr[FTN];
#pragma unroll
    for (int m = 0; m < FTM; m++)
        xsr[m] = g_xsq[rowBase + ty * 4 + (m & 3) + (m >> 2) * 64];
#pragma unroll
    for (int n = 0; n < FTN; n++)
        ssr[n] = g_ssq[colBase + tx * 4 + (n & 3) + (n >> 2) * 64];

#pragma unroll
    for (int m = 0; m < FTM; m++) {
        int row = rowBase + ty * 4 + (m & 3) + (m >> 2) * 64;
#pragma unroll
        for (int ng = 0; ng < 2; ng++) {
            float4 v;
            float* vp = &v.x;
#pragma unroll
            for (int q = 0; q < 4; q++) {
                int n = ng * 4 + q;
                float d2 = fmaf(-2.0f, acc[m][n], xsr[m] + ssr[n]);
                d2 = fmaxf(d2, 0.0f);
                vp[q] = __expf(-GAMMA_F * d2);
            }
            int col = colBase + tx * 4 + ng * 64;
            *(float4*)(out + (size_t)row * M + col) = v;
        }
    }
}

// ---------------- host: tensor map creation ----------------
typedef CUresult (*PFN_encodeTiled)(CUtensorMap*, CUtensorMapDataType, cuuint32_t, void*,
                                    const cuuint64_t*, const cuuint64_t*, const cuuint32_t*,
                                    const cuuint32_t*, CUtensorMapInterleave, CUtensorMapSwizzle,
                                    CUtensorMapL2promotion, CUtensorMapFloatOOBfill);

static bool make_map_bf16_sw64(PFN_encodeTiled enc, CUtensorMap* map, void* ptr, int boxRows) {
    cuuint64_t dims[2] = { (cuuint64_t)D_DIM, 8192 };
    cuuint64_t strides[1] = { (cuuint64_t)D_DIM * sizeof(__nv_bfloat16) };
    cuuint32_t box[2] = { (cuuint32_t)BK, (cuuint32_t)boxRows };
    cuuint32_t estr[2] = { 1, 1 };
    CUresult r = enc(map, CU_TENSOR_MAP_DATA_TYPE_BFLOAT16, 2, ptr,
                     dims, strides, box, estr,
                     CU_TENSOR_MAP_INTERLEAVE_NONE, CU_TENSOR_MAP_SWIZZLE_64B,
                     CU_TENSOR_MAP_L2_PROMOTION_L2_128B, CU_TENSOR_MAP_FLOAT_OOB_FILL_NONE);
    return r == CUDA_SUCCESS;
}

// ---------------- launch ----------------
extern "C" void kernel_launch(void* const* d_in, const int* in_sizes, int n_in,
                              void* d_out, int out_size) {
    const float* X = (const float*)d_in[0];
    const float* S = (const float*)d_in[1];
    float* out = (float*)d_out;

    int N = in_sizes[0] / D_DIM;
    int M = in_sizes[1] / D_DIM;

    int totalWarps = (N + M) / 2;
    rbf_prep_kernel<<<(totalWarps * 32 + 255) / 256, 256>>>(X, S, N, M);

    cudaFuncAttributes fa;
    fa.numRegs = 0;
    cudaFuncGetAttributes(&fa, rbf_tc_kernel);
    bool use_tc = fa.numRegs > 40;

    PFN_encodeTiled enc = nullptr;
    if (use_tc) {
        void* fn = nullptr;
        cudaDriverEntryPointQueryResult qr = cudaDriverEntryPointSymbolNotFound;
#if CUDART_VERSION >= 12050
        if (cudaGetDriverEntryPointByVersion("cuTensorMapEncodeTiled", &fn, 12000,
                                             cudaEnableDefault, &qr) != cudaSuccess ||
            qr != cudaDriverEntryPointSuccess) fn = nullptr;
#else
        if (cudaGetDriverEntryPoint("cuTensorMapEncodeTiled", &fn,
                                    cudaEnableDefault, &qr) != cudaSuccess ||
            qr != cudaDriverEntryPointSuccess) fn = nullptr;
#endif
        enc = (PFN_encodeTiled)fn;
        if (!enc) use_tc = false;
    }

    CUtensorMap tma_a, tma_b;
    if (use_tc) {
        void *xb = nullptr, *sbp = nullptr;
        if (cudaGetSymbolAddress(&xb, g_xb) != cudaSuccess ||
            cudaGetSymbolAddress(&sbp, g_sb) != cudaSuccess) {
            use_tc = false;
        } else {
            use_tc = make_map_bf16_sw64(enc, &tma_a, xb, BM) &&
                     make_map_bf16_sw64(enc, &tma_b, sbp, BN);
        }
    }

    if (use_tc) {
        cudaFuncSetAttribute(rbf_tc_kernel, cudaFuncAttributeMaxDynamicSharedMemorySize, SM_TOTAL);
        dim3 grid(M / BN, N / BM);   // (32, 64); cluster (1,2,1) pairs share colBase/B
        rbf_tc_kernel<<<grid, 256, SM_TOTAL>>>(tma_a, tma_b, out);
    } else {
        dim3 grid(M / FBN, N / FBM);
        rbf_gemm_fallback<<<grid, 256>>>(X, S, out, N, M);
    }
}

// round 16
// speedup vs baseline: 1.1034x; 1.1034x over previous
#include <cuda_runtime.h>
#include <cuda.h>
#include <cuda_bf16.h>
#include <cstdint>

#define NROWS 8192
#define MCOLS 8192
#define D_DIM 256
#define GAMMA_F (1.0f/256.0f)

// ---- tc path: 128(M) x 256(N) per CTA, bf16 SW64 TMA, 4-stage pipeline, occ 2 ----
#define BM 128
#define BN 256
#define BK 32              // bf16 elements per k-block = 64 bytes per row (SW64)
#define NBLK (D_DIM/BK)    // 8
#define NBUF 4

// smem byte offsets -- all mbars one-shot
#define SM_FULLS  0        // 8 mbars x 8B [0,64)
#define SM_DONES  64       // 4 mbars [64,96)
#define SM_FIN    96
#define SM_TMEMP  104
#define SM_SSQ    128      // 256 floats [128,1152)
#define SM_BUF0   2048     // per buf: A 8KB (128 rows x 64B) then B 16KB (256 x 64B)
#define BUF_SZ    24576
#define SM_TOTAL  (SM_BUF0 + NBUF*BUF_SZ)   // 100352 -> occ 2
#define BLK_BYTES 24576

// bf16 idesc: c=F32(1@4), a=BF16(1@7), b=BF16(1@10), N/8@17, M/16@24
#define IDESC ((1u<<4) | (1u<<7) | (1u<<10) | ((BN/8u)<<17) | ((BM/16u)<<24))

// SW64 K-major smem descriptor: layout=4, version=1, SBO=32, LBO=1
#define DESC_BASE ((4ull<<61) | (1ull<<46) | (32ull<<32) | (1ull<<16))
#define MAKE_DESC(a) (DESC_BASE | ((uint64_t)((a) >> 4) & 0x3FFF))

#if defined(__CUDA_ARCH__) && (defined(__CUDA_ARCH_FEAT_SM103_ALL) || defined(__CUDA_ARCH_FEAT_SM100_ALL) || (defined(__CUDA_ARCH_SPECIFIC__) && (__CUDA_ARCH_SPECIFIC__ >= 1000)))
#define TC_OK 1
#else
#define TC_OK 0
#endif

__device__ float g_xsq[NROWS];
__device__ float g_ssq[MCOLS];
__device__ __nv_bfloat16 g_xb[NROWS * D_DIM];
__device__ __nv_bfloat16 g_sb[MCOLS * D_DIM];

// ---------------- PTX helpers ----------------
__device__ __forceinline__ uint32_t smem_u32(const void* p) {
    uint32_t a;
    asm("{ .reg .u64 t; cvta.to.shared.u64 t, %1; cvt.u32.u64 %0, t; }" : "=r"(a) : "l"(p));
    return a;
}
__device__ __forceinline__ void mbar_init(uint32_t a, uint32_t cnt) {
    asm volatile("mbarrier.init.shared.b64 [%0], %1;" :: "r"(a), "r"(cnt) : "memory");
}
__device__ __forceinline__ void mbar_expect_tx(uint32_t a, uint32_t bytes) {
    asm volatile("mbarrier.arrive.expect_tx.shared.b64 _, [%0], %1;" :: "r"(a), "r"(bytes) : "memory");
}
__device__ __forceinline__ void mbar_wait(uint32_t a, uint32_t parity) {
    asm volatile(
        "{\n\t.reg .pred P1;\n\t"
        "WL_%=:\n\t"
        "mbarrier.try_wait.parity.acquire.cta.shared::cta.b64 P1, [%0], %1, 0x989680;\n\t"
        "@P1 bra.uni WD_%=;\n\t"
        "bra.uni WL_%=;\n\t"
        "WD_%=:\n\t}"
        :: "r"(a), "r"(parity) : "memory");
}
__device__ __forceinline__ void tma_load_2d(uint32_t smem_addr, const CUtensorMap* map,
                                            int x, int y, uint32_t mbar) {
#if TC_OK
    asm volatile(
        "cp.async.bulk.tensor.2d.shared::cta.global.tile.mbarrier::complete_tx::bytes "
        "[%0], [%1, {%2, %3}], [%4];"
        :: "r"(smem_addr), "l"(map), "r"(x), "r"(y), "r"(mbar) : "memory");
#endif
}
__device__ __forceinline__ void tmem_alloc(uint32_t smem_res, uint32_t ncols) {
#if TC_OK
    asm volatile("tcgen05.alloc.cta_group::1.sync.aligned.shared::cta.b32 [%0], %1;"
                 :: "r"(smem_res), "r"(ncols) : "memory");
#endif
}
__device__ __forceinline__ void tmem_relinq() {
#if TC_OK
    asm volatile("tcgen05.relinquish_alloc_permit.cta_group::1.sync.aligned;");
#endif
}
__device__ __forceinline__ void tmem_dealloc(uint32_t tmem, uint32_t ncols) {
#if TC_OK
    asm volatile("tcgen05.dealloc.cta_group::1.sync.aligned.b32 %0, %1;" :: "r"(tmem), "r"(ncols));
#endif
}
__device__ __forceinline__ void mma_commit(uint32_t mbar) {
#if TC_OK
    asm volatile("tcgen05.commit.cta_group::1.mbarrier::arrive::one.shared::cluster.b64 [%0];"
                 :: "r"(mbar) : "memory");
#endif
}
__device__ __forceinline__ void mma_bf16_ss(uint32_t d_tmem, uint64_t a_desc, uint64_t b_desc,
                                            uint32_t idesc, bool accum) {
#if TC_OK
    uint32_t en = accum ? 1u : 0u;
    asm volatile(
        "{\n\t.reg .pred p;\n\tsetp.ne.u32 p, %5, 0;\n\t"
        "tcgen05.mma.cta_group::1.kind::f16 [%0], %1, %2, %3, {%4, %4, %4, %4}, p;\n\t}"
        :: "r"(d_tmem), "l"(a_desc), "l"(b_desc), "r"(idesc), "r"(0u), "r"(en)
        : "memory");
#endif
}
__device__ __forceinline__ void ldtm_x32(uint32_t* r, uint32_t tmem) {
#if TC_OK
    asm volatile(
        "tcgen05.ld.sync.aligned.32x32b.x32.b32 "
        "{%0, %1, %2, %3, %4, %5, %6, %7, %8, %9, %10, %11, %12, %13, %14, %15, "
        " %16, %17, %18, %19, %20, %21, %22, %23, %24, %25, %26, %27, %28, %29, %30, %31}, [%32];"
        : "=r"(r[0]), "=r"(r[1]), "=r"(r[2]), "=r"(r[3]), "=r"(r[4]), "=r"(r[5]), "=r"(r[6]), "=r"(r[7]),
          "=r"(r[8]), "=r"(r[9]), "=r"(r[10]), "=r"(r[11]), "=r"(r[12]), "=r"(r[13]), "=r"(r[14]), "=r"(r[15]),
          "=r"(r[16]), "=r"(r[17]), "=r"(r[18]), "=r"(r[19]), "=r"(r[20]), "=r"(r[21]), "=r"(r[22]), "=r"(r[23]),
          "=r"(r[24]), "=r"(r[25]), "=r"(r[26]), "=r"(r[27]), "=r"(r[28]), "=r"(r[29]), "=r"(r[30]), "=r"(r[31])
        : "r"(tmem));
#endif
}
__device__ __forceinline__ void tmem_wait_ld() {
#if TC_OK
    asm volatile("tcgen05.wait::ld.sync.aligned;" ::: "memory");
#endif
}
__device__ __forceinline__ void fence_after() {
#if TC_OK
    asm volatile("tcgen05.fence::after_thread_sync;" ::: "memory");
#endif
}
__device__ __forceinline__ void fence_before() {
#if TC_OK
    asm volatile("tcgen05.fence::before_thread_sync;" ::: "memory");
#endif
}
__device__ __forceinline__ void fence_proxy() {
    asm volatile("fence.proxy.async.shared::cta;" ::: "memory");
}
__device__ __forceinline__ void stg_cs_v4(float* p, float a, float b, float c, float d) {
    asm volatile("st.global.cs.v4.f32 [%0], {%1, %2, %3, %4};"
                 :: "l"(p), "f"(a), "f"(b), "f"(c), "f"(d) : "memory");
}

// ---- packed f32x2 helpers ----
__device__ __forceinline__ uint64_t pack2(uint32_t lo, uint32_t hi) {
    uint64_t r;
    asm("mov.b64 %0, {%1, %2};" : "=l"(r) : "r"(lo), "r"(hi));
    return r;
}
__device__ __forceinline__ void unpack2(uint32_t& lo, uint32_t& hi, uint64_t v) {
    asm("mov.b64 {%0, %1}, %2;" : "=r"(lo), "=r"(hi) : "l"(v));
}
#if TC_OK
#define FMA2(d, a, b, c) asm("fma.rn.f32x2 %0, %1, %2, %3;" : "=l"(d) : "l"(a), "l"(b), "l"(c))
#define ADD2(d, a, b)    asm("add.rn.f32x2 %0, %1, %2;" : "=l"(d) : "l"(a), "l"(b))
#endif

// ---------------- prep kernel: fp32 -> bf16 + row norms, 4 rows per warp ----------------
__global__ void rbf_prep_kernel(const float* __restrict__ X, const float* __restrict__ S,
                                int N, int M) {
    int warp = (blockIdx.x * blockDim.x + threadIdx.x) >> 5;
    int lane = threadIdx.x & 31;
    int r0 = warp * 4;
    if (r0 >= N + M) return;

    // N and M are multiples of 4: a 4-row group never straddles the X/S boundary
    const bool isX = r0 < N;
    const int row0 = isX ? r0 : r0 - N;
    const float* srcBase = isX ? X : S;
    __nv_bfloat16* dstBase = isX ? g_xb : g_sb;

    float4 v[8];
#pragma unroll
    for (int r = 0; r < 4; r++) {
        const float* s = srcBase + (size_t)(row0 + r) * D_DIM + lane * 8;
        v[r * 2 + 0] = *(const float4*)(s);
        v[r * 2 + 1] = *(const float4*)(s + 4);
    }

    float sum[4];
#pragma unroll
    for (int r = 0; r < 4; r++) {
        float4 a = v[r * 2 + 0], b = v[r * 2 + 1];
        sum[r] = a.x * a.x + a.y * a.y + a.z * a.z + a.w * a.w
               + b.x * b.x + b.y * b.y + b.z * b.z + b.w * b.w;
    }

#pragma unroll
    for (int r = 0; r < 4; r++) {
        float4 a = v[r * 2 + 0], b = v[r * 2 + 1];
        __nv_bfloat162 b0 = __floats2bfloat162_rn(a.x, a.y);
        __nv_bfloat162 b1 = __floats2bfloat162_rn(a.z, a.w);
        __nv_bfloat162 b2 = __floats2bfloat162_rn(b.x, b.y);
        __nv_bfloat162 b3 = __floats2bfloat162_rn(b.z, b.w);
        uint4 p;
        p.x = *(uint32_t*)&b0; p.y = *(uint32_t*)&b1;
        p.z = *(uint32_t*)&b2; p.w = *(uint32_t*)&b3;
        *(uint4*)(dstBase + (size_t)(row0 + r) * D_DIM + lane * 8) = p;
    }

#pragma unroll
    for (int o = 16; o > 0; o >>= 1) {
#pragma unroll
        for (int r = 0; r < 4; r++)
            sum[r] += __shfl_xor_sync(0xffffffffu, sum[r], o);
    }
    if (lane == 0) {
        float* dq = isX ? g_xsq : g_ssq;
#pragma unroll
        for (int r = 0; r < 4; r++) dq[row0 + r] = sum[r];
    }
}

// ---------------- fused TMA(bf16,SW64) + tcgen05 GEMM + RBF epilogue ----------------
__global__ void __launch_bounds__(256, 2)
rbf_tc_kernel(const __grid_constant__ CUtensorMap tma_a,
              const __grid_constant__ CUtensorMap tma_b,
              float* __restrict__ out) {
#if TC_OK
    extern __shared__ char smem[];
    const uint32_t sb = smem_u32(smem);
    const int tid = threadIdx.x;
    const int wid = tid >> 5, lane = tid & 31;
    const int rowBase = blockIdx.y * BM;
    const int colBase = blockIdx.x * BN;

    const float A_CONST = -0.005635527503472513f;    // -gamma * log2(e)

    ((float*)(smem + SM_SSQ))[tid] = A_CONST * g_ssq[colBase + tid];
    const int sub = wid & 3;
    const int myrow = rowBase + sub * 32 + lane;
    const float xsA = A_CONST * g_xsq[myrow];

    if (tid == 0) {
#pragma unroll
        for (int i = 0; i < NBLK; i++) mbar_init(sb + SM_FULLS + i * 8, 1);
#pragma unroll
        for (int i = 0; i < 4; i++) mbar_init(sb + SM_DONES + i * 8, 1);
        mbar_init(sb + SM_FIN, 1);
        fence_proxy();
    }
    if (wid == 0) { tmem_alloc(sb + SM_TMEMP, 256); tmem_relinq(); }
    __syncthreads();

    uint32_t tmem;
    asm volatile("ld.shared.b32 %0, [%1];" : "=r"(tmem) : "r"(sb + SM_TMEMP));

    if (tid == 0) {
        uint32_t abuf[NBUF], bbuf[NBUF];
        uint64_t ad[NBUF], bd[NBUF];
#pragma unroll
        for (int b = 0; b < NBUF; b++) {
            abuf[b] = sb + SM_BUF0 + b * BUF_SZ;
            bbuf[b] = abuf[b] + 8192;
            ad[b] = MAKE_DESC(abuf[b]);
            bd[b] = MAKE_DESC(bbuf[b]);
        }

        // prologue: k-blocks 0..3 into bufs 0..3
#pragma unroll
        for (int p = 0; p < NBUF; p++) {
            mbar_expect_tx(sb + SM_FULLS + p * 8, BLK_BYTES);
            tma_load_2d(abuf[p], &tma_a, p * BK, rowBase, sb + SM_FULLS + p * 8);
            tma_load_2d(bbuf[p], &tma_b, p * BK, colBase, sb + SM_FULLS + p * 8);
        }

#pragma unroll
        for (int i = 0; i < NBLK; i++) {
            const int buf = i & 3;
            mbar_wait(sb + SM_FULLS + i * 8, 0);      // one-shot: parity 0
#pragma unroll
            for (int s = 0; s < 2; s++)               // 2 x K=16 bf16 steps
                mma_bf16_ss(tmem, ad[buf] + s * 2, bd[buf] + s * 2, IDESC, (i > 0) || (s > 0));
            if (i < NBLK - 4) mma_commit(sb + SM_DONES + i * 8);
            else if (i == NBLK - 1) mma_commit(sb + SM_FIN);
            if (i + 4 < NBLK) {
                mbar_wait(sb + SM_DONES + i * 8, 0);
                const int k0 = (i + 4) * BK;
                mbar_expect_tx(sb + SM_FULLS + (i + 4) * 8, BLK_BYTES);
                tma_load_2d(abuf[buf], &tma_a, k0, rowBase, sb + SM_FULLS + (i + 4) * 8);
                tma_load_2d(bbuf[buf], &tma_b, k0, colBase, sb + SM_FULLS + (i + 4) * 8);
            }
        }
    }

    mbar_wait(sb + SM_FIN, 0);
    fence_after();

    // ---- packed f32x2 epilogue, LDTM double-buffered ----
    const float C2 = -2.0f * A_CONST;
    const float MAGIC = 12582912.0f;
    const uint64_t xsAp   = pack2(__float_as_uint(xsA), __float_as_uint(xsA));
    const uint64_t C2p    = pack2(__float_as_uint(C2), __float_as_uint(C2));
    const uint64_t MAGICp = pack2(__float_as_uint(MAGIC), __float_as_uint(MAGIC));
    const uint64_t NMAGp  = pack2(__float_as_uint(-MAGIC), __float_as_uint(-MAGIC));
    const uint64_t NEG1p  = pack2(__float_as_uint(-1.0f), __float_as_uint(-1.0f));
    const uint64_t C4p  = pack2(__float_as_uint(9.6181291e-3f), __float_as_uint(9.6181291e-3f));
    const uint64_t C3p  = pack2(__float_as_uint(5.5504115e-2f), __float_as_uint(5.5504115e-2f));
    const uint64_t C2pp = pack2(__float_as_uint(2.4022649e-1f), __float_as_uint(2.4022649e-1f));
    const uint64_t C1p  = pack2(__float_as_uint(6.9314718e-1f), __float_as_uint(6.9314718e-1f));
    const uint64_t C0p  = pack2(__float_as_uint(1.0f), __float_as_uint(1.0f));

    const char* ssqA = (const char*)(smem + SM_SSQ);
    const int half = wid >> 2;

    uint32_t regsA[32], regsB[32];
    ldtm_x32(regsA, tmem + half * 128);
    tmem_wait_ld();

#pragma unroll
    for (int ch = 0; ch < 4; ch++) {
        uint32_t* cur = (ch & 1) ? regsB : regsA;
        uint32_t* nxt = (ch & 1) ? regsA : regsB;
        const int col0 = half * 128 + ch * 32;
        if (ch < 3) ldtm_x32(nxt, tmem + col0 + 32);   // prefetch next chunk
        const size_t obase = (size_t)myrow * MCOLS + colBase + col0;
#pragma unroll
        for (int j4 = 0; j4 < 8; j4++) {
            float vv[4];
#pragma unroll
            for (int jp = 0; jp < 2; jp++) {
                const int j = j4 * 4 + jp * 2;
                uint64_t sAp = *(const uint64_t*)(ssqA + (col0 + j) * 4);
                uint64_t crp = pack2(cur[j], cur[j + 1]);
                uint64_t up, tp, zp, yp, rp, pp;
                ADD2(up, sAp, xsAp);
                FMA2(tp, crp, C2p, up);
                ADD2(zp, tp, MAGICp);
                ADD2(yp, zp, NMAGp);
                FMA2(rp, yp, NEG1p, tp);
                FMA2(pp, rp, C4p, C3p);
                FMA2(pp, rp, pp, C2pp);
                FMA2(pp, rp, pp, C1p);
                FMA2(pp, rp, pp, C0p);
                uint32_t z0, z1, p0, p1;
                unpack2(z0, z1, zp);
                unpack2(p0, p1, pp);
                vv[jp * 2 + 0] = __int_as_float((int)p0 + ((int)z0 << 23));
                vv[jp * 2 + 1] = __int_as_float((int)p1 + ((int)z1 << 23));
            }
            stg_cs_v4(out + obase + j4 * 4, vv[0], vv[1], vv[2], vv[3]);
        }
        if (ch < 3) tmem_wait_ld();
    }

    fence_before();
    __syncthreads();
    if (wid == 0) tmem_dealloc(tmem, 256);
#endif  // TC_OK
}

// ---------------- SIMT fallback (proven R1 kernel) ----------------
#define FBM 128
#define FBN 128
#define FBK 32
#define FTM 8
#define FTN 8
#define FPAD 4

__global__ void __launch_bounds__(256, 2)
rbf_gemm_fallback(const float* __restrict__ X, const float* __restrict__ S,
                  float* __restrict__ out, int N, int M) {
    __shared__ float As[FBK][FBM + FPAD];
    __shared__ float Bs[FBK][FBN + FPAD];

    const int tid = threadIdx.x;
    const int tx = tid & 15;
    const int ty = tid >> 4;
    const int rowBase = blockIdx.y * FBM;
    const int colBase = blockIdx.x * FBN;

    float acc[FTM][FTN];
#pragma unroll
    for (int m = 0; m < FTM; m++)
#pragma unroll
        for (int n = 0; n < FTN; n++) acc[m][n] = 0.0f;

    for (int k0 = 0; k0 < D_DIM; k0 += FBK) {
#pragma unroll
        for (int i = 0; i < 4; i++) {
            int f = tid + i * 256;
            int r = f >> 3;
            int c = (f & 7) * 4;
            float4 a = *(const float4*)(X + (size_t)(rowBase + r) * D_DIM + k0 + c);
            As[c + 0][r] = a.x; As[c + 1][r] = a.y;
            As[c + 2][r] = a.z; As[c + 3][r] = a.w;
            float4 b = *(const float4*)(S + (size_t)(colBase + r) * D_DIM + k0 + c);
            Bs[c + 0][r] = b.x; Bs[c + 1][r] = b.y;
            Bs[c + 2][r] = b.z; Bs[c + 3][r] = b.w;
        }
        __syncthreads();

#pragma unroll 8
        for (int k = 0; k < FBK; k++) {
            float ar[FTM], br[FTN];
            float4 a0 = *(const float4*)&As[k][ty * 4];
            float4 a1 = *(const float4*)&As[k][ty * 4 + 64];
            float4 b0 = *(const float4*)&Bs[k][tx * 4];
            float4 b1 = *(const float4*)&Bs[k][tx * 4 + 64];
            ar[0] = a0.x; ar[1] = a0.y; ar[2] = a0.z; ar[3] = a0.w;
            ar[4] = a1.x; ar[5] = a1.y; ar[6] = a1.z; ar[7] = a1.w;
            br[0] = b0.x; br[1] = b0.y; br[2] = b0.z; br[3] = b0.w;
            br[4] = b1.x; br[5] = b1.y; br[6] = b1.z; br[7] = b1.w;
#pragma unroll
            for (int m = 0; m < FTM; m++)
#pragma unroll
                for (int n = 0; n < FTN; n++)
                    acc[m][n] = fmaf(ar[m], br[n], acc[m][n]);
        }
        __syncthreads();
    }

    float xsr[FTM], ssr[FTN];
#pragma unroll
    for (int m = 0; m < FTM; m++)
        xsr[m] = g_xsq[rowBase + ty * 4 + (m & 3) + (m >> 2) * 64];
#pragma unroll
    for (int n = 0; n < FTN; n++)
        ssr[n] = g_ssq[colBase + tx * 4 + (n & 3) + (n >> 2) * 64];

#pragma unroll
    for (int m = 0; m < FTM; m++) {
        int row = rowBase + ty * 4 + (m & 3) + (m >> 2) * 64;
#pragma unroll
        for (int ng = 0; ng < 2; ng++) {
            float4 v;
            float* vp = &v.x;
#pragma unroll
            for (int q = 0; q < 4; q++) {
                int n = ng * 4 + q;
                float d2 = fmaf(-2.0f, acc[m][n], xsr[m] + ssr[n]);
                d2 = fmaxf(d2, 0.0f);
                vp[q] = __expf(-GAMMA_F * d2);
            }
            int col = colBase + tx * 4 + ng * 64;
            *(float4*)(out + (size_t)row * M + col) = v;
        }
    }
}

// ---------------- host: tensor map creation ----------------
typedef CUresult (*PFN_encodeTiled)(CUtensorMap*, CUtensorMapDataType, cuuint32_t, void*,
                                    const cuuint64_t*, const cuuint64_t*, const cuuint32_t*,
                                    const cuuint32_t*, CUtensorMapInterleave, CUtensorMapSwizzle,
                                    CUtensorMapL2promotion, CUtensorMapFloatOOBfill);

static bool make_map_bf16_sw64(PFN_encodeTiled enc, CUtensorMap* map, void* ptr, int boxRows) {
    cuuint64_t dims[2] = { (cuuint64_t)D_DIM, 8192 };
    cuuint64_t strides[1] = { (cuuint64_t)D_DIM * sizeof(__nv_bfloat16) };
    cuuint32_t box[2] = { (cuuint32_t)BK, (cuuint32_t)boxRows };
    cuuint32_t estr[2] = { 1, 1 };
    CUresult r = enc(map, CU_TENSOR_MAP_DATA_TYPE_BFLOAT16, 2, ptr,
                     dims, strides, box, estr,
                     CU_TENSOR_MAP_INTERLEAVE_NONE, CU_TENSOR_MAP_SWIZZLE_64B,
                     CU_TENSOR_MAP_L2_PROMOTION_L2_128B, CU_TENSOR_MAP_FLOAT_OOB_FILL_NONE);
    return r == CUDA_SUCCESS;
}

// ---------------- launch ----------------
extern "C" void kernel_launch(void* const* d_in, const int* in_sizes, int n_in,
                              void* d_out, int out_size) {
    const float* X = (const float*)d_in[0];
    const float* S = (const float*)d_in[1];
    float* out = (float*)d_out;

    int N = in_sizes[0] / D_DIM;
    int M = in_sizes[1] / D_DIM;

    // prep: 4 rows per warp
    int totalWarps = (N + M) / 4;
    rbf_prep_kernel<<<(totalWarps * 32 + 255) / 256, 256>>>(X, S, N, M);

    cudaFuncAttributes fa;
    fa.numRegs = 0;
    cudaFuncGetAttributes(&fa, rbf_tc_kernel);
    bool use_tc = fa.numRegs > 40;

    PFN_encodeTiled enc = nullptr;
    if (use_tc) {
        void* fn = nullptr;
        cudaDriverEntryPointQueryResult qr = cudaDriverEntryPointSymbolNotFound;
#if CUDART_VERSION >= 12050
        if (cudaGetDriverEntryPointByVersion("cuTensorMapEncodeTiled", &fn, 12000,
                                             cudaEnableDefault, &qr) != cudaSuccess ||
            qr != cudaDriverEntryPointSuccess) fn = nullptr;
#else
        if (cudaGetDriverEntryPoint("cuTensorMapEncodeTiled", &fn,
                                    cudaEnableDefault, &qr) != cudaSuccess ||
            qr != cudaDriverEntryPointSuccess) fn = nullptr;
#endif
        enc = (PFN_encodeTiled)fn;
        if (!enc) use_tc = false;
    }

    CUtensorMap tma_a, tma_b;
    if (use_tc) {
        void *xb = nullptr, *sbp = nullptr;
        if (cudaGetSymbolAddress(&xb, g_xb) != cudaSuccess ||
            cudaGetSymbolAddress(&sbp, g_sb) != cudaSuccess) {
            use_tc = false;
        } else {
            use_tc = make_map_bf16_sw64(enc, &tma_a, xb, BM) &&
                     make_map_bf16_sw64(enc, &tma_b, sbp, BN);
        }
    }

    if (use_tc) {
        cudaFuncSetAttribute(rbf_tc_kernel, cudaFuncAttributeMaxDynamicSharedMemorySize, SM_TOTAL);
        dim3 grid(M / BN, N / BM);
        rbf_tc_kernel<<<grid, 256, SM_TOTAL>>>(tma_a, tma_b, out);
    } else {
        dim3 grid(M / FBN, N / FBM);
        rbf_gemm_fallback<<<grid, 256>>>(X, S, out, N, M);
    }
}

// round 17
// speedup vs baseline: 2.0227x; 1.8332x over previous
#include <cuda_runtime.h>
#include <cuda.h>
#include <cuda_bf16.h>
#include <cstdint>

#define NROWS 8192
#define MCOLS 8192
#define D_DIM 256
#define GAMMA_F (1.0f/256.0f)

// ---- tc path: 128(M) x 256(N) per CTA, bf16 SW64 TMA in, TMA-store out, occ 2 ----
#define BM 128
#define BN 256
#define BK 32              // bf16 elements per k-block = 64 bytes per row (SW64)
#define NBLK (D_DIM/BK)    // 8
#define NBUF 4

// smem byte offsets -- all mbars one-shot
#define SM_FULLS  0        // 8 mbars x 8B [0,64)
#define SM_DONES  64       // 4 mbars [64,96)
#define SM_FIN    96
#define SM_TMEMP  104
#define SM_SSQ    128      // 256 floats [128,1152)
#define SM_BUF0   2048     // per buf: A 8KB (128 rows x 64B) then B 16KB (256 x 64B)
#define BUF_SZ    24576
#define SM_TOTAL  (SM_BUF0 + NBUF*BUF_SZ)   // 100352 -> occ 2
#define BLK_BYTES 24576
// epilogue staging (reuses pipeline buffers after GEMM): per half 2 x 16KB
#define STAGE_SZ  16384

// bf16 idesc: c=F32(1@4), a=BF16(1@7), b=BF16(1@10), N/8@17, M/16@24
#define IDESC ((1u<<4) | (1u<<7) | (1u<<10) | ((BN/8u)<<17) | ((BM/16u)<<24))

// SW64 K-major smem descriptor: layout=4, version=1, SBO=32, LBO=1
#define DESC_BASE ((4ull<<61) | (1ull<<46) | (32ull<<32) | (1ull<<16))
#define MAKE_DESC(a) (DESC_BASE | ((uint64_t)((a) >> 4) & 0x3FFF))

#if defined(__CUDA_ARCH__) && (defined(__CUDA_ARCH_FEAT_SM103_ALL) || defined(__CUDA_ARCH_FEAT_SM100_ALL) || (defined(__CUDA_ARCH_SPECIFIC__) && (__CUDA_ARCH_SPECIFIC__ >= 1000)))
#define TC_OK 1
#else
#define TC_OK 0
#endif

__device__ float g_xsq[NROWS];
__device__ float g_ssq[MCOLS];
__device__ __nv_bfloat16 g_xb[NROWS * D_DIM];
__device__ __nv_bfloat16 g_sb[MCOLS * D_DIM];

// ---------------- PTX helpers ----------------
__device__ __forceinline__ uint32_t smem_u32(const void* p) {
    uint32_t a;
    asm("{ .reg .u64 t; cvta.to.shared.u64 t, %1; cvt.u32.u64 %0, t; }" : "=r"(a) : "l"(p));
    return a;
}
__device__ __forceinline__ void mbar_init(uint32_t a, uint32_t cnt) {
    asm volatile("mbarrier.init.shared.b64 [%0], %1;" :: "r"(a), "r"(cnt) : "memory");
}
__device__ __forceinline__ void mbar_expect_tx(uint32_t a, uint32_t bytes) {
    asm volatile("mbarrier.arrive.expect_tx.shared.b64 _, [%0], %1;" :: "r"(a), "r"(bytes) : "memory");
}
__device__ __forceinline__ void mbar_wait(uint32_t a, uint32_t parity) {
    asm volatile(
        "{\n\t.reg .pred P1;\n\t"
        "WL_%=:\n\t"
        "mbarrier.try_wait.parity.acquire.cta.shared::cta.b64 P1, [%0], %1, 0x989680;\n\t"
        "@P1 bra.uni WD_%=;\n\t"
        "bra.uni WL_%=;\n\t"
        "WD_%=:\n\t}"
        :: "r"(a), "r"(parity) : "memory");
}
__device__ __forceinline__ void tma_load_2d(uint32_t smem_addr, const CUtensorMap* map,
                                            int x, int y, uint32_t mbar) {
#if TC_OK
    asm volatile(
        "cp.async.bulk.tensor.2d.shared::cta.global.tile.mbarrier::complete_tx::bytes "
        "[%0], [%1, {%2, %3}], [%4];"
        :: "r"(smem_addr), "l"(map), "r"(x), "r"(y), "r"(mbar) : "memory");
#endif
}
__device__ __forceinline__ void tma_store_2d(const CUtensorMap* map, int x, int y,
                                             uint32_t smem_addr) {
#if TC_OK
    asm volatile(
        "cp.async.bulk.tensor.2d.global.shared::cta.tile.bulk_group "
        "[%0, {%1, %2}], [%3];"
        :: "l"(map), "r"(x), "r"(y), "r"(smem_addr) : "memory");
#endif
}
__device__ __forceinline__ void tma_store_commit() {
#if TC_OK
    asm volatile("cp.async.bulk.commit_group;" ::: "memory");
#endif
}
template<int N> __device__ __forceinline__ void tma_store_wait() {
#if TC_OK
    asm volatile("cp.async.bulk.wait_group %0;" :: "n"(N) : "memory");
#endif
}
__device__ __forceinline__ void tmem_alloc(uint32_t smem_res, uint32_t ncols) {
#if TC_OK
    asm volatile("tcgen05.alloc.cta_group::1.sync.aligned.shared::cta.b32 [%0], %1;"
                 :: "r"(smem_res), "r"(ncols) : "memory");
#endif
}
__device__ __forceinline__ void tmem_relinq() {
#if TC_OK
    asm volatile("tcgen05.relinquish_alloc_permit.cta_group::1.sync.aligned;");
#endif
}
__device__ __forceinline__ void tmem_dealloc(uint32_t tmem, uint32_t ncols) {
#if TC_OK
    asm volatile("tcgen05.dealloc.cta_group::1.sync.aligned.b32 %0, %1;" :: "r"(tmem), "r"(ncols));
#endif
}
__device__ __forceinline__ void mma_commit(uint32_t mbar) {
#if TC_OK
    asm volatile("tcgen05.commit.cta_group::1.mbarrier::arrive::one.shared::cluster.b64 [%0];"
                 :: "r"(mbar) : "memory");
#endif
}
__device__ __forceinline__ void mma_bf16_ss(uint32_t d_tmem, uint64_t a_desc, uint64_t b_desc,
                                            uint32_t idesc, bool accum) {
#if TC_OK
    uint32_t en = accum ? 1u : 0u;
    asm volatile(
        "{\n\t.reg .pred p;\n\tsetp.ne.u32 p, %5, 0;\n\t"
        "tcgen05.mma.cta_group::1.kind::f16 [%0], %1, %2, %3, {%4, %4, %4, %4}, p;\n\t}"
        :: "r"(d_tmem), "l"(a_desc), "l"(b_desc), "r"(idesc), "r"(0u), "r"(en)
        : "memory");
#endif
}
__device__ __forceinline__ void ldtm_x32(uint32_t* r, uint32_t tmem) {
#if TC_OK
    asm volatile(
        "tcgen05.ld.sync.aligned.32x32b.x32.b32 "
        "{%0, %1, %2, %3, %4, %5, %6, %7, %8, %9, %10, %11, %12, %13, %14, %15, "
        " %16, %17, %18, %19, %20, %21, %22, %23, %24, %25, %26, %27, %28, %29, %30, %31}, [%32];"
        : "=r"(r[0]), "=r"(r[1]), "=r"(r[2]), "=r"(r[3]), "=r"(r[4]), "=r"(r[5]), "=r"(r[6]), "=r"(r[7]),
          "=r"(r[8]), "=r"(r[9]), "=r"(r[10]), "=r"(r[11]), "=r"(r[12]), "=r"(r[13]), "=r"(r[14]), "=r"(r[15]),
          "=r"(r[16]), "=r"(r[17]), "=r"(r[18]), "=r"(r[19]), "=r"(r[20]), "=r"(r[21]), "=r"(r[22]), "=r"(r[23]),
          "=r"(r[24]), "=r"(r[25]), "=r"(r[26]), "=r"(r[27]), "=r"(r[28]), "=r"(r[29]), "=r"(r[30]), "=r"(r[31])
        : "r"(tmem));
#endif
}
__device__ __forceinline__ void tmem_wait_ld() {
#if TC_OK
    asm volatile("tcgen05.wait::ld.sync.aligned;" ::: "memory");
#endif
}
__device__ __forceinline__ void fence_after() {
#if TC_OK
    asm volatile("tcgen05.fence::after_thread_sync;" ::: "memory");
#endif
}
__device__ __forceinline__ void fence_before() {
#if TC_OK
    asm volatile("tcgen05.fence::before_thread_sync;" ::: "memory");
#endif
}
__device__ __forceinline__ void fence_proxy() {
    asm volatile("fence.proxy.async.shared::cta;" ::: "memory");
}
__device__ __forceinline__ void named_bar(int id, int nthreads) {
    asm volatile("bar.sync %0, %1;" :: "r"(id), "r"(nthreads) : "memory");
}
__device__ __forceinline__ void sts128(uint32_t addr, float a, float b, float c, float d) {
    asm volatile("st.shared.v4.f32 [%0], {%1, %2, %3, %4};"
                 :: "r"(addr), "f"(a), "f"(b), "f"(c), "f"(d) : "memory");
}

// ---- packed f32x2 helpers ----
__device__ __forceinline__ uint64_t pack2(uint32_t lo, uint32_t hi) {
    uint64_t r;
    asm("mov.b64 %0, {%1, %2};" : "=l"(r) : "r"(lo), "r"(hi));
    return r;
}
__device__ __forceinline__ void unpack2(uint32_t& lo, uint32_t& hi, uint64_t v) {
    asm("mov.b64 {%0, %1}, %2;" : "=r"(lo), "=r"(hi) : "l"(v));
}
#if TC_OK
#define FMA2(d, a, b, c) asm("fma.rn.f32x2 %0, %1, %2, %3;" : "=l"(d) : "l"(a), "l"(b), "l"(c))
#define ADD2(d, a, b)    asm("add.rn.f32x2 %0, %1, %2;" : "=l"(d) : "l"(a), "l"(b))
#endif

// ---------------- prep kernel: fp32 -> bf16 + row norms, 4 rows per warp ----------------
__global__ void rbf_prep_kernel(const float* __restrict__ X, const float* __restrict__ S,
                                int N, int M) {
    int warp = (blockIdx.x * blockDim.x + threadIdx.x) >> 5;
    int lane = threadIdx.x & 31;
    int r0 = warp * 4;
    if (r0 >= N + M) return;

    const bool isX = r0 < N;
    const int row0 = isX ? r0 : r0 - N;
    const float* srcBase = isX ? X : S;
    __nv_bfloat16* dstBase = isX ? g_xb : g_sb;

    float4 v[8];
#pragma unroll
    for (int r = 0; r < 4; r++) {
        const float* s = srcBase + (size_t)(row0 + r) * D_DIM + lane * 8;
        v[r * 2 + 0] = *(const float4*)(s);
        v[r * 2 + 1] = *(const float4*)(s + 4);
    }

    float sum[4];
#pragma unroll
    for (int r = 0; r < 4; r++) {
        float4 a = v[r * 2 + 0], b = v[r * 2 + 1];
        sum[r] = a.x * a.x + a.y * a.y + a.z * a.z + a.w * a.w
               + b.x * b.x + b.y * b.y + b.z * b.z + b.w * b.w;
    }

#pragma unroll
    for (int r = 0; r < 4; r++) {
        float4 a = v[r * 2 + 0], b = v[r * 2 + 1];
        __nv_bfloat162 b0 = __floats2bfloat162_rn(a.x, a.y);
        __nv_bfloat162 b1 = __floats2bfloat162_rn(a.z, a.w);
        __nv_bfloat162 b2 = __floats2bfloat162_rn(b.x, b.y);
        __nv_bfloat162 b3 = __floats2bfloat162_rn(b.z, b.w);
        uint4 p;
        p.x = *(uint32_t*)&b0; p.y = *(uint32_t*)&b1;
        p.z = *(uint32_t*)&b2; p.w = *(uint32_t*)&b3;
        *(uint4*)(dstBase + (size_t)(row0 + r) * D_DIM + lane * 8) = p;
    }

#pragma unroll
    for (int o = 16; o > 0; o >>= 1) {
#pragma unroll
        for (int r = 0; r < 4; r++)
            sum[r] += __shfl_xor_sync(0xffffffffu, sum[r], o);
    }
    if (lane == 0) {
        float* dq = isX ? g_xsq : g_ssq;
#pragma unroll
        for (int r = 0; r < 4; r++) dq[row0 + r] = sum[r];
    }
}

// ---------------- fused TMA(bf16,SW64) + tcgen05 GEMM + TMA-store RBF epilogue ----------------
__global__ void __launch_bounds__(256, 2)
rbf_tc_kernel(const __grid_constant__ CUtensorMap tma_a,
              const __grid_constant__ CUtensorMap tma_b,
              const __grid_constant__ CUtensorMap tma_o) {
#if TC_OK
    extern __shared__ char smem[];
    const uint32_t sb = smem_u32(smem);
    const int tid = threadIdx.x;
    const int wid = tid >> 5, lane = tid & 31;
    const int rowBase = blockIdx.y * BM;
    const int colBase = blockIdx.x * BN;

    const float A_CONST = -0.005635527503472513f;    // -gamma * log2(e)

    ((float*)(smem + SM_SSQ))[tid] = A_CONST * g_ssq[colBase + tid];
    const int sub = wid & 3;
    const int rloc = sub * 32 + lane;                 // local row 0..127
    const float xsA = A_CONST * g_xsq[rowBase + rloc];

    if (tid == 0) {
#pragma unroll
        for (int i = 0; i < NBLK; i++) mbar_init(sb + SM_FULLS + i * 8, 1);
#pragma unroll
        for (int i = 0; i < 4; i++) mbar_init(sb + SM_DONES + i * 8, 1);
        mbar_init(sb + SM_FIN, 1);
        fence_proxy();
    }
    if (wid == 0) { tmem_alloc(sb + SM_TMEMP, 256); tmem_relinq(); }
    __syncthreads();

    uint32_t tmem;
    asm volatile("ld.shared.b32 %0, [%1];" : "=r"(tmem) : "r"(sb + SM_TMEMP));

    if (tid == 0) {
        uint32_t abuf[NBUF], bbuf[NBUF];
        uint64_t ad[NBUF], bd[NBUF];
#pragma unroll
        for (int b = 0; b < NBUF; b++) {
            abuf[b] = sb + SM_BUF0 + b * BUF_SZ;
            bbuf[b] = abuf[b] + 8192;
            ad[b] = MAKE_DESC(abuf[b]);
            bd[b] = MAKE_DESC(bbuf[b]);
        }

        // prologue: k-blocks 0..3 into bufs 0..3
#pragma unroll
        for (int p = 0; p < NBUF; p++) {
            mbar_expect_tx(sb + SM_FULLS + p * 8, BLK_BYTES);
            tma_load_2d(abuf[p], &tma_a, p * BK, rowBase, sb + SM_FULLS + p * 8);
            tma_load_2d(bbuf[p], &tma_b, p * BK, colBase, sb + SM_FULLS + p * 8);
        }

#pragma unroll
        for (int i = 0; i < NBLK; i++) {
            const int buf = i & 3;
            mbar_wait(sb + SM_FULLS + i * 8, 0);      // one-shot: parity 0
#pragma unroll
            for (int s = 0; s < 2; s++)               // 2 x K=16 bf16 steps
                mma_bf16_ss(tmem, ad[buf] + s * 2, bd[buf] + s * 2, IDESC, (i > 0) || (s > 0));
            if (i < NBLK - 4) mma_commit(sb + SM_DONES + i * 8);
            else if (i == NBLK - 1) mma_commit(sb + SM_FIN);
            if (i + 4 < NBLK) {
                mbar_wait(sb + SM_DONES + i * 8, 0);
                const int k0 = (i + 4) * BK;
                mbar_expect_tx(sb + SM_FULLS + (i + 4) * 8, BLK_BYTES);
                tma_load_2d(abuf[buf], &tma_a, k0, rowBase, sb + SM_FULLS + (i + 4) * 8);
                tma_load_2d(bbuf[buf], &tma_b, k0, colBase, sb + SM_FULLS + (i + 4) * 8);
            }
        }
    }

    mbar_wait(sb + SM_FIN, 0);
    fence_after();

    // ---- packed f32x2 epilogue -> smem staging -> TMA store (full-line writes) ----
    const float C2 = -2.0f * A_CONST;
    const float MAGIC = 12582912.0f;
    const uint64_t xsAp   = pack2(__float_as_uint(xsA), __float_as_uint(xsA));
    const uint64_t C2p    = pack2(__float_as_uint(C2), __float_as_uint(C2));
    const uint64_t MAGICp = pack2(__float_as_uint(MAGIC), __float_as_uint(MAGIC));
    const uint64_t NMAGp  = pack2(__float_as_uint(-MAGIC), __float_as_uint(-MAGIC));
    const uint64_t NEG1p  = pack2(__float_as_uint(-1.0f), __float_as_uint(-1.0f));
    const uint64_t C4p  = pack2(__float_as_uint(9.6181291e-3f), __float_as_uint(9.6181291e-3f));
    const uint64_t C3p  = pack2(__float_as_uint(5.5504115e-2f), __float_as_uint(5.5504115e-2f));
    const uint64_t C2pp = pack2(__float_as_uint(2.4022649e-1f), __float_as_uint(2.4022649e-1f));
    const uint64_t C1p  = pack2(__float_as_uint(6.9314718e-1f), __float_as_uint(6.9314718e-1f));
    const uint64_t C0p  = pack2(__float_as_uint(1.0f), __float_as_uint(1.0f));

    const char* ssqA = (const char*)(smem + SM_SSQ);
    const int half = wid >> 2;
    const int barid = 1 + half;                       // named barrier per 128-thread half
    const bool issuer = (lane == 0 && sub == 0);      // tid 0 / tid 128
    const uint32_t stage0 = sb + SM_BUF0 + half * 2 * STAGE_SZ;

    uint32_t regsA[32], regsB[32];
    ldtm_x32(regsA, tmem + half * 128);
    tmem_wait_ld();

#pragma unroll
    for (int ch = 0; ch < 4; ch++) {
        uint32_t* cur = (ch & 1) ? regsB : regsA;
        uint32_t* nxt = (ch & 1) ? regsA : regsB;
        const int col0 = half * 128 + ch * 32;
        if (ch < 3) ldtm_x32(nxt, tmem + col0 + 32);   // prefetch next chunk

        if (ch >= 2) {
            if (issuer) tma_store_wait<1>();           // staging buf (ch&1) drained
            named_bar(barid, 128);
        }
        const uint32_t stg = stage0 + (ch & 1) * STAGE_SZ;

#pragma unroll
        for (int j4 = 0; j4 < 8; j4++) {
            float vv[4];
#pragma unroll
            for (int jp = 0; jp < 2; jp++) {
                const int j = j4 * 4 + jp * 2;
                uint64_t sAp = *(const uint64_t*)(ssqA + (col0 + j) * 4);
                uint64_t crp = pack2(cur[j], cur[j + 1]);
                uint64_t up, tp, zp, yp, rp, pp;
                ADD2(up, sAp, xsAp);
                FMA2(tp, crp, C2p, up);
                ADD2(zp, tp, MAGICp);
                ADD2(yp, zp, NMAGp);
                FMA2(rp, yp, NEG1p, tp);
                FMA2(pp, rp, C4p, C3p);
                FMA2(pp, rp, pp, C2pp);
                FMA2(pp, rp, pp, C1p);
                FMA2(pp, rp, pp, C0p);
                uint32_t z0, z1, p0, p1;
                unpack2(z0, z1, zp);
                unpack2(p0, p1, pp);
                vv[jp * 2 + 0] = __int_as_float((int)p0 + ((int)z0 << 23));
                vv[jp * 2 + 1] = __int_as_float((int)p1 + ((int)z1 << 23));
            }
            // SW128-swizzled staging: row rloc, 16B chunk j4
            uint32_t off = (uint32_t)(rloc * 128 + j4 * 16);
            uint32_t sw = off ^ ((off >> 3) & 0x70);
            sts128(stg + sw, vv[0], vv[1], vv[2], vv[3]);
        }
        named_bar(barid, 128);
        if (issuer) {
            fence_proxy();
            tma_store_2d(&tma_o, colBase + col0, rowBase, stg);
            tma_store_commit();
        }
        if (ch < 3) tmem_wait_ld();
    }

    if (issuer) tma_store_wait<0>();                   // smem must outlive stores
    fence_before();
    __syncthreads();
    if (wid == 0) tmem_dealloc(tmem, 256);
#endif  // TC_OK
}

// ---------------- SIMT fallback (proven R1 kernel) ----------------
#define FBM 128
#define FBN 128
#define FBK 32
#define FTM 8
#define FTN 8
#define FPAD 4

__global__ void __launch_bounds__(256, 2)
rbf_gemm_fallback(const float* __restrict__ X, const float* __restrict__ S,
                  float* __restrict__ out, int N, int M) {
    __shared__ float As[FBK][FBM + FPAD];
    __shared__ float Bs[FBK][FBN + FPAD];

    const int tid = threadIdx.x;
    const int tx = tid & 15;
    const int ty = tid >> 4;
    const int rowBase = blockIdx.y * FBM;
    const int colBase = blockIdx.x * FBN;

    float acc[FTM][FTN];
#pragma unroll
    for (int m = 0; m < FTM; m++)
#pragma unroll
        for (int n = 0; n < FTN; n++) acc[m][n] = 0.0f;

    for (int k0 = 0; k0 < D_DIM; k0 += FBK) {
#pragma unroll
        for (int i = 0; i < 4; i++) {
            int f = tid + i * 256;
            int r = f >> 3;
            int c = (f & 7) * 4;
            float4 a = *(const float4*)(X + (size_t)(rowBase + r) * D_DIM + k0 + c);
            As[c + 0][r] = a.x; As[c + 1][r] = a.y;
            As[c + 2][r] = a.z; As[c + 3][r] = a.w;
            float4 b = *(const float4*)(S + (size_t)(colBase + r) * D_DIM + k0 + c);
            Bs[c + 0][r] = b.x; Bs[c + 1][r] = b.y;
            Bs[c + 2][r] = b.z; Bs[c + 3][r] = b.w;
        }
        __syncthreads();

#pragma unroll 8
        for (int k = 0; k < FBK; k++) {
            float ar[FTM], br[FTN];
            float4 a0 = *(const float4*)&As[k][ty * 4];
            float4 a1 = *(const float4*)&As[k][ty * 4 + 64];
            float4 b0 = *(const float4*)&Bs[k][tx * 4];
            float4 b1 = *(const float4*)&Bs[k][tx * 4 + 64];
            ar[0] = a0.x; ar[1] = a0.y; ar[2] = a0.z; ar[3] = a0.w;
            ar[4] = a1.x; ar[5] = a1.y; ar[6] = a1.z; ar[7] = a1.w;
            br[0] = b0.x; br[1] = b0.y; br[2] = b0.z; br[3] = b0.w;
            br[4] = b1.x; br[5] = b1.y; br[6] = b1.z; br[7] = b1.w;
#pragma unroll
            for (int m = 0; m < FTM; m++)
#pragma unroll
                for (int n = 0; n < FTN; n++)
                    acc[m][n] = fmaf(ar[m], br[n], acc[m][n]);
        }
        __syncthreads();
    }

    float xsr[FTM], ssr[FTN];
#pragma unroll
    for (int m = 0; m < FTM; m++)
        xsr[m] = g_xsq[rowBase + ty * 4 + (m & 3) + (m >> 2) * 64];
#pragma unroll
    for (int n = 0; n < FTN; n++)
        ssr[n] = g_ssq[colBase + tx * 4 + (n & 3) + (n >> 2) * 64];

#pragma unroll
    for (int m = 0; m < FTM; m++) {
        int row = rowBase + ty * 4 + (m & 3) + (m >> 2) * 64;
#pragma unroll
        for (int ng = 0; ng < 2; ng++) {
            float4 v;
            float* vp = &v.x;
#pragma unroll
            for (int q = 0; q < 4; q++) {
                int n = ng * 4 + q;
                float d2 = fmaf(-2.0f, acc[m][n], xsr[m] + ssr[n]);
                d2 = fmaxf(d2, 0.0f);
                vp[q] = __expf(-GAMMA_F * d2);
            }
            int col = colBase + tx * 4 + ng * 64;
            *(float4*)(out + (size_t)row * M + col) = v;
        }
    }
}

// ---------------- host: tensor map creation ----------------
typedef CUresult (*PFN_encodeTiled)(CUtensorMap*, CUtensorMapDataType, cuuint32_t, void*,
                                    const cuuint64_t*, const cuuint64_t*, const cuuint32_t*,
                                    const cuuint32_t*, CUtensorMapInterleave, CUtensorMapSwizzle,
                                    CUtensorMapL2promotion, CUtensorMapFloatOOBfill);

static bool make_map_bf16_sw64(PFN_encodeTiled enc, CUtensorMap* map, void* ptr, int boxRows) {
    cuuint64_t dims[2] = { (cuuint64_t)D_DIM, 8192 };
    cuuint64_t strides[1] = { (cuuint64_t)D_DIM * sizeof(__nv_bfloat16) };
    cuuint32_t box[2] = { (cuuint32_t)BK, (cuuint32_t)boxRows };
    cuuint32_t estr[2] = { 1, 1 };
    CUresult r = enc(map, CU_TENSOR_MAP_DATA_TYPE_BFLOAT16, 2, ptr,
                     dims, strides, box, estr,
                     CU_TENSOR_MAP_INTERLEAVE_NONE, CU_TENSOR_MAP_SWIZZLE_64B,
                     CU_TENSOR_MAP_L2_PROMOTION_L2_128B, CU_TENSOR_MAP_FLOAT_OOB_FILL_NONE);
    return r == CUDA_SUCCESS;
}

static bool make_map_out(PFN_encodeTiled enc, CUtensorMap* map, void* ptr) {
    cuuint64_t dims[2] = { (cuuint64_t)MCOLS, (cuuint64_t)NROWS };
    cuuint64_t strides[1] = { (cuuint64_t)MCOLS * sizeof(float) };
    cuuint32_t box[2] = { 32, 128 };                  // 32 cols (128B) x 128 rows
    cuuint32_t estr[2] = { 1, 1 };
    CUresult r = enc(map, CU_TENSOR_MAP_DATA_TYPE_FLOAT32, 2, ptr,
                     dims, strides, box, estr,
                     CU_TENSOR_MAP_INTERLEAVE_NONE, CU_TENSOR_MAP_SWIZZLE_128B,
                     CU_TENSOR_MAP_L2_PROMOTION_L2_128B, CU_TENSOR_MAP_FLOAT_OOB_FILL_NONE);
    return r == CUDA_SUCCESS;
}

// ---------------- launch ----------------
extern "C" void kernel_launch(void* const* d_in, const int* in_sizes, int n_in,
                              void* d_out, int out_size) {
    const float* X = (const float*)d_in[0];
    const float* S = (const float*)d_in[1];
    float* out = (float*)d_out;

    int N = in_sizes[0] / D_DIM;
    int M = in_sizes[1] / D_DIM;

    int totalWarps = (N + M) / 4;
    rbf_prep_kernel<<<(totalWarps * 32 + 255) / 256, 256>>>(X, S, N, M);

    cudaFuncAttributes fa;
    fa.numRegs = 0;
    cudaFuncGetAttributes(&fa, rbf_tc_kernel);
    bool use_tc = fa.numRegs > 40;

    PFN_encodeTiled enc = nullptr;
    if (use_tc) {
        void* fn = nullptr;
        cudaDriverEntryPointQueryResult qr = cudaDriverEntryPointSymbolNotFound;
#if CUDART_VERSION >= 12050
        if (cudaGetDriverEntryPointByVersion("cuTensorMapEncodeTiled", &fn, 12000,
                                             cudaEnableDefault, &qr) != cudaSuccess ||
            qr != cudaDriverEntryPointSuccess) fn = nullptr;
#else
        if (cudaGetDriverEntryPoint("cuTensorMapEncodeTiled", &fn,
                                    cudaEnableDefault, &qr) != cudaSuccess ||
            qr != cudaDriverEntryPointSuccess) fn = nullptr;
#endif
        enc = (PFN_encodeTiled)fn;
        if (!enc) use_tc = false;
    }

    CUtensorMap tma_a, tma_b, tma_o;
    if (use_tc) {
        void *xb = nullptr, *sbp = nullptr;
        if (cudaGetSymbolAddress(&xb, g_xb) != cudaSuccess ||
            cudaGetSymbolAddress(&sbp, g_sb) != cudaSuccess) {
            use_tc = false;
        } else {
            use_tc = make_map_bf16_sw64(enc, &tma_a, xb, BM) &&
                     make_map_bf16_sw64(enc, &tma_b, sbp, BN) &&
                     make_map_out(enc, &tma_o, out);
        }
    }

    if (use_tc) {
        cudaFuncSetAttribute(rbf_tc_kernel, cudaFuncAttributeMaxDynamicSharedMemorySize, SM_TOTAL);
        dim3 grid(M / BN, N / BM);
        rbf_tc_kernel<<<grid, 256, SM_TOTAL>>>(tma_a, tma_b, tma_o);
    } else {
        dim3 grid(M / FBN, N / FBM);
        rbf_gemm_fallback<<<grid, 256>>>(X, S, out, N, M);
    }
}